// round 4
// baseline (speedup 1.0000x reference)
#include <cuda_runtime.h>
#include <cuda_bf16.h>
#include <cstdint>

#define B_   2
#define S_   2048
#define T_   4096          // B*S
#define DIM_ 512
#define INNER_ 1024
#define I2_  2048
#define NH_  16
#define DH_  64
#define KSZ_ 4
#define EPS_ 5e-5f
#define NORM_EPS_ 1e-6f
#define CAP_ 15.0f
#define IFSPLIT 16

// ---------------- scratch (device globals; no allocation allowed) ----------
__device__ float g_xinner[T_ * I2_];
__device__ float g_xconv [T_ * INNER_];
__device__ float g_q     [T_ * INNER_];
__device__ float g_k     [T_ * INNER_];
__device__ float g_v     [T_ * INNER_];
__device__ float g_ifpart[IFSPLIT * T_ * 32];
__device__ float g_if    [T_ * 32];
__device__ float g_gv    [B_ * NH_ * S_];
__device__ float g_Mv    [B_ * NH_ * S_];
__device__ float g_env   [B_ * NH_ * S_];
__device__ float g_hout  [T_ * INNER_];

// ---------------- tf32 mma helpers -----------------------------------------
__device__ __forceinline__ float tfstore(float x) {
    uint32_t r; asm("cvt.rna.tf32.f32 %0, %1;" : "=r"(r) : "f"(x));
    return __uint_as_float(r);
}
__device__ __forceinline__ void mma8(float* c, const uint32_t* a,
                                     uint32_t b0, uint32_t b1) {
    asm volatile(
        "mma.sync.aligned.m16n8k8.row.col.f32.tf32.tf32.f32 "
        "{%0,%1,%2,%3}, {%4,%5,%6,%7}, {%8,%9}, {%0,%1,%2,%3};"
        : "+f"(c[0]), "+f"(c[1]), "+f"(c[2]), "+f"(c[3])
        : "r"(a[0]), "r"(a[1]), "r"(a[2]), "r"(a[3]), "r"(b0), "r"(b1));
}

// ---------------- tf32 NT GEMM: C[M,N] = A[M,K] * B[N,K]^T ------------------
__global__ __launch_bounds__(256) void gemm_nt_tf32(
    const float* __restrict__ A, const float* __restrict__ Bm,
    float* __restrict__ C, int M, int N, int K)
{
    __shared__ float As[16][136];
    __shared__ float Bs[16][136];
    int bm = blockIdx.y * 128, bn = blockIdx.x * 128;
    int tid = threadIdx.x;
    int warp = tid >> 5, lane = tid & 31;
    int wm = warp & 3;
    int wn = warp >> 2;
    int g = lane >> 2, tig = lane & 3;
    float acc[2][8][4];
#pragma unroll
    for (int mt = 0; mt < 2; mt++)
#pragma unroll
        for (int nt = 0; nt < 8; nt++)
#pragma unroll
            for (int i = 0; i < 4; i++) acc[mt][nt][i] = 0.f;

    int r = tid >> 1, ks = (tid & 1) * 8;
    const float* Ag = A + (long)(bm + r) * K + ks;
    const float* Bg = Bm + (long)(bn + r) * K + ks;

    for (int k0 = 0; k0 < K; k0 += 16) {
        float4 av0 = *(const float4*)(Ag + k0);
        float4 av1 = *(const float4*)(Ag + k0 + 4);
        float4 bv0 = *(const float4*)(Bg + k0);
        float4 bv1 = *(const float4*)(Bg + k0 + 4);
        __syncthreads();
        As[ks + 0][r] = tfstore(av0.x); As[ks + 1][r] = tfstore(av0.y);
        As[ks + 2][r] = tfstore(av0.z); As[ks + 3][r] = tfstore(av0.w);
        As[ks + 4][r] = tfstore(av1.x); As[ks + 5][r] = tfstore(av1.y);
        As[ks + 6][r] = tfstore(av1.z); As[ks + 7][r] = tfstore(av1.w);
        Bs[ks + 0][r] = tfstore(bv0.x); Bs[ks + 1][r] = tfstore(bv0.y);
        Bs[ks + 2][r] = tfstore(bv0.z); Bs[ks + 3][r] = tfstore(bv0.w);
        Bs[ks + 4][r] = tfstore(bv1.x); Bs[ks + 5][r] = tfstore(bv1.y);
        Bs[ks + 6][r] = tfstore(bv1.z); Bs[ks + 7][r] = tfstore(bv1.w);
        __syncthreads();
#pragma unroll
        for (int kk = 0; kk < 16; kk += 8) {
            uint32_t af[2][4];
#pragma unroll
            for (int mt = 0; mt < 2; mt++) {
                int row = wm * 32 + mt * 16;
                af[mt][0] = __float_as_uint(As[kk + tig][row + g]);
                af[mt][1] = __float_as_uint(As[kk + tig][row + g + 8]);
                af[mt][2] = __float_as_uint(As[kk + tig + 4][row + g]);
                af[mt][3] = __float_as_uint(As[kk + tig + 4][row + g + 8]);
            }
#pragma unroll
            for (int nt = 0; nt < 8; nt++) {
                int col = wn * 64 + nt * 8 + g;
                uint32_t b0 = __float_as_uint(Bs[kk + tig][col]);
                uint32_t b1 = __float_as_uint(Bs[kk + tig + 4][col]);
                mma8(acc[0][nt], af[0], b0, b1);
                mma8(acc[1][nt], af[1], b0, b1);
            }
        }
    }
#pragma unroll
    for (int mt = 0; mt < 2; mt++)
#pragma unroll
        for (int nt = 0; nt < 8; nt++) {
            int row = bm + wm * 32 + mt * 16 + g;
            int col = bn + wn * 64 + nt * 8 + tig * 2;
            C[(long)row * N + col]       = acc[mt][nt][0];
            C[(long)row * N + col + 1]   = acc[mt][nt][1];
            C[(long)(row + 8) * N + col]     = acc[mt][nt][2];
            C[(long)(row + 8) * N + col + 1] = acc[mt][nt][3];
        }
}

// ---------------- causal conv1d (KSZ=4) + SiLU -----------------------------
__global__ __launch_bounds__(256) void conv_silu_kernel(
    const float* __restrict__ xinner, const float* __restrict__ cw,
    const float* __restrict__ cb, float* __restrict__ xconv)
{
    int idx = blockIdx.x * 256 + threadIdx.x;
    int c = idx & (INNER_ - 1);
    int token = idx >> 10;
    int s = token & (S_ - 1);
    int b = token >> 11;
    float acc = cb[c];
#pragma unroll
    for (int j = 0; j < KSZ_; j++) {
        int sp = s - (KSZ_ - 1) + j;
        if (sp >= 0) acc += xinner[(long)(b * S_ + sp) * I2_ + c] * cw[c * KSZ_ + j];
    }
    xconv[idx] = acc / (1.f + __expf(-acc));
}

// ---------------- per-head q/k/v projections (64x64 per head) --------------
__global__ __launch_bounds__(256) void qkv_kernel(
    const float* __restrict__ xconv, const float* __restrict__ xinner,
    const float* __restrict__ Wq, const float* __restrict__ Wk,
    const float* __restrict__ Wv,
    float* __restrict__ q, float* __restrict__ k, float* __restrict__ v)
{
    int tt = blockIdx.x;
    int h  = blockIdx.y;
    int which = blockIdx.z;
    const float* src; int srcStride; const float* W; float* dst;
    if (which == 0)      { src = xconv;  srcStride = INNER_; W = Wq; dst = q; }
    else if (which == 1) { src = xconv;  srcStride = INNER_; W = Wk; dst = k; }
    else                 { src = xinner; srcStride = I2_;    W = Wv; dst = v; }

    __shared__ float Xs[64][68];
    __shared__ float Ws[64][68];
    int tid = threadIdx.x, tx = tid & 15, ty = tid >> 4;
    int tok0 = tt * 64;
#pragma unroll
    for (int i = 0; i < 4; i++) {
        int c = tid + i * 256;        // 1024 chunks of 4
        int s = c >> 4, d0 = (c & 15) * 4;
        float4 xv = *(const float4*)&src[(long)(tok0 + s) * srcStride + h * DH_ + d0];
        float4 wv = *(const float4*)&W[h * DH_ * DH_ + s * DH_ + d0];
        Xs[d0 + 0][s] = xv.x; Xs[d0 + 1][s] = xv.y;
        Xs[d0 + 2][s] = xv.z; Xs[d0 + 3][s] = xv.w;
        Ws[d0 + 0][s] = wv.x; Ws[d0 + 1][s] = wv.y;
        Ws[d0 + 2][s] = wv.z; Ws[d0 + 3][s] = wv.w;
    }
    __syncthreads();
    float acc[4][4];
#pragma unroll
    for (int i = 0; i < 4; i++)
#pragma unroll
        for (int j = 0; j < 4; j++) acc[i][j] = 0.f;
#pragma unroll 16
    for (int d = 0; d < 64; d++) {
        float4 a = *(const float4*)&Xs[d][ty * 4];
        float4 b = *(const float4*)&Ws[d][tx * 4];
        float av[4] = {a.x,a.y,a.z,a.w};
        float bv[4] = {b.x,b.y,b.z,b.w};
#pragma unroll
        for (int i = 0; i < 4; i++)
#pragma unroll
            for (int j = 0; j < 4; j++) acc[i][j] += av[i] * bv[j];
    }
#pragma unroll
    for (int i = 0; i < 4; i++) {
        float4 o = {acc[i][0],acc[i][1],acc[i][2],acc[i][3]};
        *(float4*)&dst[(long)(tok0 + ty * 4 + i) * INNER_ + h * DH_ + tx * 4] = o;
    }
}

// ---------------- i/f gate GEMM, split-K partials ---------------------------
// grid (T/64, IFSPLIT); K chunk = 3072/IFSPLIT = 192 (6 sub-chunks of 32)
__global__ __launch_bounds__(256) void ifgate_partial_kernel(
    const float* __restrict__ q, const float* __restrict__ k,
    const float* __restrict__ v, const float* __restrict__ Wif,
    float* __restrict__ part)
{
    int tt = blockIdx.x;
    int z  = blockIdx.y;
    __shared__ float As[32][68];
    __shared__ float Ws[32][36];
    int tid = threadIdx.x;
    int ty = tid >> 3;
    int tx = tid & 7;
    float acc[2][4] = {{0,0,0,0},{0,0,0,0}};
    int c0 = z * 6;
    for (int cc = 0; cc < 6; cc++) {
        int e0 = (c0 + cc) * 32;
        const float* src = (e0 < 1024) ? q : (e0 < 2048) ? k : v;
        int ec = e0 & 1023;
#pragma unroll
        for (int i = 0; i < 8; i++) {
            int el = tid + i * 256; int s = el >> 5, e = el & 31;
            As[e][s] = src[(long)(tt * 64 + s) * INNER_ + ec + e];
        }
#pragma unroll
        for (int i = 0; i < 4; i++) {
            int el = tid + i * 256; int g = el >> 5, e = el & 31;
            Ws[e][g] = Wif[g * 3072 + e0 + e];
        }
        __syncthreads();
#pragma unroll 8
        for (int e = 0; e < 32; e++) {
            float a0 = As[e][ty * 2], a1 = As[e][ty * 2 + 1];
            float4 b = *(const float4*)&Ws[e][tx * 4];
            float bv[4] = {b.x,b.y,b.z,b.w};
#pragma unroll
            for (int j = 0; j < 4; j++) { acc[0][j] += a0 * bv[j]; acc[1][j] += a1 * bv[j]; }
        }
        __syncthreads();
    }
#pragma unroll
    for (int i = 0; i < 2; i++) {
        int token = tt * 64 + ty * 2 + i;
        float4 o = {acc[i][0],acc[i][1],acc[i][2],acc[i][3]};
        *(float4*)&part[((long)z * T_ + token) * 32 + tx * 4] = o;
    }
}

__global__ __launch_bounds__(256) void ifreduce_kernel(
    const float* __restrict__ part, const float* __restrict__ bif,
    float* __restrict__ ifp)
{
    int idx = blockIdx.x * 256 + threadIdx.x;
    int g = idx & 31;
    float s = 0.f;
#pragma unroll
    for (int z = 0; z < IFSPLIT; z++) s += part[(long)z * T_ * 32 + idx];
    float val = s + bif[g];
    ifp[idx] = CAP_ * tanhf(val * (1.0f / CAP_));
}

// ---------------- gate prefix scan per (b,h) --------------------------------
__global__ __launch_bounds__(256) void gate_scan_kernel(
    const float* __restrict__ ifp, float* __restrict__ gg,
    float* __restrict__ gM, float* __restrict__ gEn)
{
    const float NEGINF = -3.0e38f;
    int bh = blockIdx.x;
    int b = bh / NH_, h = bh % NH_;
    int tid = threadIdx.x;
    __shared__ float sbuf[256];
    const int VPT = 8;
    float li[VPT], cs[VPT];
    float csum = 0.f;
#pragma unroll
    for (int j = 0; j < VPT; j++) {
        int s = tid * VPT + j;
        long base = (long)(b * S_ + s) * 32;
        float f = ifp[base + 16 + h];
        li[j] = ifp[base + h];
        float ls = fminf(f, 0.f) - log1pf(__expf(-fabsf(f)));
        csum += ls;
        cs[j] = csum;
    }
    sbuf[tid] = csum; __syncthreads();
    for (int off = 1; off < 256; off <<= 1) {
        float vv = (tid >= off) ? sbuf[tid - off] : 0.f;
        __syncthreads();
        sbuf[tid] += vv;
        __syncthreads();
    }
    float excl = sbuf[tid] - csum;
    float Fc[VPT], gv[VPT], mcs[VPT];
    float mx = NEGINF;
#pragma unroll
    for (int j = 0; j < VPT; j++) {
        Fc[j] = excl + cs[j];
        gv[j] = li[j] - Fc[j];
        mx = fmaxf(mx, gv[j]);
        mcs[j] = mx;
    }
    __syncthreads();
    sbuf[tid] = mx; __syncthreads();
    for (int off = 1; off < 256; off <<= 1) {
        float vv = (tid >= off) ? sbuf[tid - off] : NEGINF;
        __syncthreads();
        sbuf[tid] = fmaxf(sbuf[tid], vv);
        __syncthreads();
    }
    float emax = (tid == 0) ? NEGINF : sbuf[tid - 1];
#pragma unroll
    for (int j = 0; j < VPT; j++) {
        int s = tid * VPT + j;
        long o = (long)bh * S_ + s;
        float M = fmaxf(emax, mcs[j]);
        gg[o] = gv[j];
        gM[o] = M;
        gEn[o] = __expf(-(Fc[j] + M));
    }
}

// ---------------- mLSTM attention (tf32 mma, prefetch + Q-hoist) ------------
__global__ __launch_bounds__(256, 2) void mlstm_attn_tf32(
    const float* __restrict__ q, const float* __restrict__ k,
    const float* __restrict__ v, const float* __restrict__ gg,
    const float* __restrict__ gM, const float* __restrict__ gEn,
    const float* __restrict__ xinner, const float* __restrict__ xconv,
    const float* __restrict__ norm_w, const float* __restrict__ skip,
    float* __restrict__ hout)
{
    int bh = blockIdx.y;
    int b = bh >> 4, h = bh & 15;
    extern __shared__ float sm[];
    float* Qs  = sm;                 // [64][68] s-major
    float* Ks  = Qs + 64 * 68;       // [64][68] d-major; later H[s][d]
    float* Ps  = Ks + 64 * 68;       // [64][68] s-major
    float* Vs  = Ps + 64 * 68;       // [80][68] d-major (row 64 = ones)
    float* Msv = Vs + 80 * 68;       // [64]
    float* gsv = Msv + 64;           // [64]
    float* rsv = gsv + 64;           // [64]

    int tid = threadIdx.x;
    int warp = tid >> 5, lane = tid & 31;
    int wm = warp & 3, wn = warp >> 2;
    int g = lane >> 2, tig = lane & 3;
    int srow0 = wm * 16 + g, srow1 = srow0 + 8;

    // ones rows of Vs: once per block
    for (int i = tid; i < 16 * 68; i += 256) Vs[64 * 68 + i] = 0.f;
    __syncthreads();
    if (tid < 64) Vs[64 * 68 + tid] = 1.0f;

    for (int rep = 0; rep < 2; rep++) {
        int qt = rep ? (31 - (int)blockIdx.x) : (int)blockIdx.x;
        int tok0 = b * S_ + qt * 64;

        __syncthreads();
#pragma unroll
        for (int i = 0; i < 4; i++) {
            int c = tid + i * 256; int s = c >> 4, d0 = (c & 15) * 4;
            float4 qv = *(const float4*)&q[(long)(tok0 + s) * INNER_ + h * DH_ + d0];
            Qs[s * 68 + d0 + 0] = tfstore(qv.x);
            Qs[s * 68 + d0 + 1] = tfstore(qv.y);
            Qs[s * 68 + d0 + 2] = tfstore(qv.z);
            Qs[s * 68 + d0 + 3] = tfstore(qv.w);
        }
        if (tid < 64) Msv[tid] = gM[(long)bh * S_ + qt * 64 + tid];
        __syncthreads();
        float Mi0 = Msv[srow0], Mi1 = Msv[srow1];

        // hoist Q fragments (constant over kt loop)
        uint32_t qf[8][4];
#pragma unroll
        for (int k08 = 0; k08 < 8; k08++) {
            int k0 = k08 * 8;
            qf[k08][0] = __float_as_uint(Qs[srow0 * 68 + k0 + tig]);
            qf[k08][1] = __float_as_uint(Qs[srow1 * 68 + k0 + tig]);
            qf[k08][2] = __float_as_uint(Qs[srow0 * 68 + k0 + tig + 4]);
            qf[k08][3] = __float_as_uint(Qs[srow1 * 68 + k0 + tig + 4]);
        }

        float acc[5][4];
#pragma unroll
        for (int nt = 0; nt < 5; nt++)
#pragma unroll
            for (int i = 0; i < 4; i++) acc[nt][i] = 0.f;

        // prefetch kt=0 tile into registers
        float4 kr[4], vr[4];
        {
            int ktok = b * S_;  // kt=0
            int ktok2 = ktok + 0;
#pragma unroll
            for (int i = 0; i < 4; i++) {
                int c = tid + i * 256; int t = c >> 4, d0 = (c & 15) * 4;
                kr[i] = *(const float4*)&k[(long)(ktok2 + t) * INNER_ + h * DH_ + d0];
                vr[i] = *(const float4*)&v[(long)(ktok2 + t) * INNER_ + h * DH_ + d0];
            }
        }

        for (int kt = 0; kt <= qt; kt++) {
            __syncthreads();   // prev PV / epilogue readers done with Ks/Vs
#pragma unroll
            for (int i = 0; i < 4; i++) {
                int c = tid + i * 256; int t = c >> 4, d0 = (c & 15) * 4;
                Ks[(d0 + 0) * 68 + t] = tfstore(kr[i].x);
                Ks[(d0 + 1) * 68 + t] = tfstore(kr[i].y);
                Ks[(d0 + 2) * 68 + t] = tfstore(kr[i].z);
                Ks[(d0 + 3) * 68 + t] = tfstore(kr[i].w);
                Vs[(d0 + 0) * 68 + t] = tfstore(vr[i].x);
                Vs[(d0 + 1) * 68 + t] = tfstore(vr[i].y);
                Vs[(d0 + 2) * 68 + t] = tfstore(vr[i].z);
                Vs[(d0 + 3) * 68 + t] = tfstore(vr[i].w);
            }
            if (tid < 64) gsv[tid] = gg[(long)bh * S_ + kt * 64 + tid];
            __syncthreads();

            // QK^T
            float p[4][4];
#pragma unroll
            for (int nt = 0; nt < 4; nt++)
#pragma unroll
                for (int i = 0; i < 4; i++) p[nt][i] = 0.f;
#pragma unroll
            for (int k08 = 0; k08 < 8; k08++) {
                int k0 = k08 * 8;
#pragma unroll
                for (int nt = 0; nt < 4; nt++) {
                    int t = wn * 32 + nt * 8 + g;
                    uint32_t b0 = __float_as_uint(Ks[(k0 + tig) * 68 + t]);
                    uint32_t b1 = __float_as_uint(Ks[(k0 + tig + 4) * 68 + t]);
                    mma8(p[nt], qf[k08], b0, b1);
                }
            }

            // prefetch next kt tile (latency covered by gating + PV)
            if (kt < qt) {
                int ktok = b * S_ + (kt + 1) * 64;
#pragma unroll
                for (int i = 0; i < 4; i++) {
                    int c = tid + i * 256; int t = c >> 4, d0 = (c & 15) * 4;
                    kr[i] = *(const float4*)&k[(long)(ktok + t) * INNER_ + h * DH_ + d0];
                    vr[i] = *(const float4*)&v[(long)(ktok + t) * INNER_ + h * DH_ + d0];
                }
            }

            // gate + mask + store P (tf32)
            bool diag = (kt == qt);
#pragma unroll
            for (int nt = 0; nt < 4; nt++) {
                int c0c = wn * 32 + nt * 8 + tig * 2;
                float gv0 = gsv[c0c], gv1 = gsv[c0c + 1];
                float e00 = (diag && c0c     > srow0) ? 0.f : p[nt][0] * 0.125f * __expf(gv0 - Mi0);
                float e01 = (diag && c0c + 1 > srow0) ? 0.f : p[nt][1] * 0.125f * __expf(gv1 - Mi0);
                float e10 = (diag && c0c     > srow1) ? 0.f : p[nt][2] * 0.125f * __expf(gv0 - Mi1);
                float e11 = (diag && c0c + 1 > srow1) ? 0.f : p[nt][3] * 0.125f * __expf(gv1 - Mi1);
                Ps[srow0 * 68 + c0c]     = tfstore(e00);
                Ps[srow0 * 68 + c0c + 1] = tfstore(e01);
                Ps[srow1 * 68 + c0c]     = tfstore(e10);
                Ps[srow1 * 68 + c0c + 1] = tfstore(e11);
            }
            __syncthreads();

            // P @ [V | 1]
#pragma unroll
            for (int k08 = 0; k08 < 8; k08++) {
                int k0 = k08 * 8;
                uint32_t af[4];
                af[0] = __float_as_uint(Ps[srow0 * 68 + k0 + tig]);
                af[1] = __float_as_uint(Ps[srow1 * 68 + k0 + tig]);
                af[2] = __float_as_uint(Ps[srow0 * 68 + k0 + tig + 4]);
                af[3] = __float_as_uint(Ps[srow1 * 68 + k0 + tig + 4]);
#pragma unroll
                for (int nt = 0; nt < 5; nt++) {
                    int d = wn * 40 + nt * 8 + g;
                    uint32_t b0 = __float_as_uint(Vs[d * 68 + k0 + tig]);
                    uint32_t b1 = __float_as_uint(Vs[d * 68 + k0 + tig + 4]);
                    mma8(acc[nt], af, b0, b1);
                }
            }
        }
        __syncthreads();

        // write H into Ks scratch ([s][d] stride 68) and rsum into rsv
#pragma unroll
        for (int nt = 0; nt < 5; nt++) {
            int dcol = wn * 40 + nt * 8 + tig * 2;
            if (dcol < 64) {
                Ks[srow0 * 68 + dcol]     = acc[nt][0];
                Ks[srow0 * 68 + dcol + 1] = acc[nt][1];
                Ks[srow1 * 68 + dcol]     = acc[nt][2];
                Ks[srow1 * 68 + dcol + 1] = acc[nt][3];
            } else if (dcol == 64) {
                rsv[srow0] = acc[nt][0];
                rsv[srow1] = acc[nt][2];
            }
        }
        __syncthreads();

        // epilogue
        int r2 = tid >> 2, qd = tid & 3;
        float n = fmaxf(fabsf(rsv[r2]), gEn[(long)bh * S_ + qt * 64 + r2]);
        float inv = 1.f / (n + EPS_);
        float hv[16];
        float ss = 0.f;
#pragma unroll
        for (int u = 0; u < 16; u++) {
            hv[u] = Ks[r2 * 68 + qd * 16 + u] * inv;
            ss += hv[u] * hv[u];
        }
        Qs[r2 * 4 + qd] = ss;
        __syncthreads();
        float sumsq = Qs[r2 * 4 + 0] + Qs[r2 * 4 + 1] + Qs[r2 * 4 + 2] + Qs[r2 * 4 + 3];
        float rrms = rsqrtf(sumsq * (1.f / 64.f) + NORM_EPS_);
        int token = tok0 + r2;
#pragma unroll
        for (int u = 0; u < 16; u++) {
            int c = h * DH_ + qd * 16 + u;
            float hn = hv[u] * rrms * (1.f + norm_w[c]);
            float ht = hn + skip[c] * xconv[(long)token * INNER_ + c];
            float z = xinner[(long)token * I2_ + INNER_ + c];
            float out = ht * (z / (1.f + __expf(-z)));
            hout[(long)token * INNER_ + c] = out;
        }
    }
}

// ---------------------------------------------------------------------------
extern "C" void kernel_launch(void* const* d_in, const int* in_sizes, int n_in,
                              void* d_out, int out_size)
{
    const float* x      = (const float*)d_in[0];
    const float* W_up   = (const float*)d_in[1];
    const float* W_q    = (const float*)d_in[2];
    const float* W_k    = (const float*)d_in[3];
    const float* W_v    = (const float*)d_in[4];
    const float* conv_w = (const float*)d_in[5];
    const float* conv_b = (const float*)d_in[6];
    const float* W_if   = (const float*)d_in[7];
    const float* b_if   = (const float*)d_in[8];
    const float* norm_w = (const float*)d_in[9];
    const float* skip   = (const float*)d_in[10];
    const float* W_down = (const float*)d_in[11];
    float* out = (float*)d_out;

    float *xinner, *xconv, *qp, *kp, *vp, *ifpart, *ifp, *gv, *Mv, *env, *hout;
    cudaGetSymbolAddress((void**)&xinner, g_xinner);
    cudaGetSymbolAddress((void**)&xconv,  g_xconv);
    cudaGetSymbolAddress((void**)&qp,     g_q);
    cudaGetSymbolAddress((void**)&kp,     g_k);
    cudaGetSymbolAddress((void**)&vp,     g_v);
    cudaGetSymbolAddress((void**)&ifpart, g_ifpart);
    cudaGetSymbolAddress((void**)&ifp,    g_if);
    cudaGetSymbolAddress((void**)&gv,     g_gv);
    cudaGetSymbolAddress((void**)&Mv,     g_Mv);
    cudaGetSymbolAddress((void**)&env,    g_env);
    cudaGetSymbolAddress((void**)&hout,   g_hout);

    const int ATTN_SMEM = (3 * 64 * 68 + 80 * 68 + 192) * (int)sizeof(float);
    cudaFuncSetAttribute(mlstm_attn_tf32,
                         cudaFuncAttributeMaxDynamicSharedMemorySize, ATTN_SMEM);

    gemm_nt_tf32<<<dim3(I2_ / 128, T_ / 128), 256>>>(x, W_up, xinner, T_, I2_, DIM_);
    conv_silu_kernel<<<(T_ * INNER_) / 256, 256>>>(xinner, conv_w, conv_b, xconv);
    qkv_kernel<<<dim3(T_ / 64, NH_, 3), 256>>>(xconv, xinner, W_q, W_k, W_v, qp, kp, vp);
    ifgate_partial_kernel<<<dim3(T_ / 64, IFSPLIT), 256>>>(qp, kp, vp, W_if, ifpart);
    ifreduce_kernel<<<(T_ * 32) / 256, 256>>>(ifpart, b_if, ifp);
    gate_scan_kernel<<<B_ * NH_, 256>>>(ifp, gv, Mv, env);
    mlstm_attn_tf32<<<dim3(S_ / 128, B_ * NH_), 256, ATTN_SMEM>>>(
        qp, kp, vp, gv, Mv, env, xinner, xconv, norm_w, skip, hout);
    gemm_nt_tf32<<<dim3(DIM_ / 128, T_ / 128), 256>>>(hout, W_down, out, T_, DIM_, INNER_);
}

// round 5
// speedup vs baseline: 1.2060x; 1.2060x over previous
#include <cuda_runtime.h>
#include <cuda_bf16.h>
#include <cstdint>

#define B_   2
#define S_   2048
#define T_   4096          // B*S
#define DIM_ 512
#define INNER_ 1024
#define I2_  2048
#define NH_  16
#define DH_  64
#define KSZ_ 4
#define EPS_ 5e-5f
#define NORM_EPS_ 1e-6f
#define CAP_ 15.0f
#define IFSPLIT 16

// ---------------- scratch (device globals; no allocation allowed) ----------
__device__ float g_xinner[T_ * I2_];
__device__ float g_xconv [T_ * INNER_];
__device__ float g_q     [T_ * INNER_];
__device__ float g_k     [T_ * INNER_];
__device__ float g_v     [T_ * INNER_];
__device__ float g_ifpart[IFSPLIT * T_ * 32];
__device__ float g_if    [T_ * 32];
__device__ float g_gv    [B_ * NH_ * S_];
__device__ float g_Mv    [B_ * NH_ * S_];
__device__ float g_env   [B_ * NH_ * S_];
__device__ float g_hout  [T_ * INNER_];

// ---------------- tf32 mma helpers -----------------------------------------
__device__ __forceinline__ float tfstore(float x) {
    uint32_t r; asm("cvt.rna.tf32.f32 %0, %1;" : "=r"(r) : "f"(x));
    return __uint_as_float(r);
}
__device__ __forceinline__ void mma8(float* c, const uint32_t* a,
                                     uint32_t b0, uint32_t b1) {
    asm volatile(
        "mma.sync.aligned.m16n8k8.row.col.f32.tf32.tf32.f32 "
        "{%0,%1,%2,%3}, {%4,%5,%6,%7}, {%8,%9}, {%0,%1,%2,%3};"
        : "+f"(c[0]), "+f"(c[1]), "+f"(c[2]), "+f"(c[3])
        : "r"(a[0]), "r"(a[1]), "r"(a[2]), "r"(a[3]), "r"(b0), "r"(b1));
}

// ---------------- tf32 NT GEMM: C[M,N] = A[M,K] * B[N,K]^T ------------------
__global__ __launch_bounds__(256) void gemm_nt_tf32(
    const float* __restrict__ A, const float* __restrict__ Bm,
    float* __restrict__ C, int M, int N, int K)
{
    __shared__ float As[16][136];
    __shared__ float Bs[16][136];
    int bm = blockIdx.y * 128, bn = blockIdx.x * 128;
    int tid = threadIdx.x;
    int warp = tid >> 5, lane = tid & 31;
    int wm = warp & 3;
    int wn = warp >> 2;
    int g = lane >> 2, tig = lane & 3;
    float acc[2][8][4];
#pragma unroll
    for (int mt = 0; mt < 2; mt++)
#pragma unroll
        for (int nt = 0; nt < 8; nt++)
#pragma unroll
            for (int i = 0; i < 4; i++) acc[mt][nt][i] = 0.f;

    int r = tid >> 1, ks = (tid & 1) * 8;
    const float* Ag = A + (long)(bm + r) * K + ks;
    const float* Bg = Bm + (long)(bn + r) * K + ks;

    for (int k0 = 0; k0 < K; k0 += 16) {
        float4 av0 = *(const float4*)(Ag + k0);
        float4 av1 = *(const float4*)(Ag + k0 + 4);
        float4 bv0 = *(const float4*)(Bg + k0);
        float4 bv1 = *(const float4*)(Bg + k0 + 4);
        __syncthreads();
        As[ks + 0][r] = tfstore(av0.x); As[ks + 1][r] = tfstore(av0.y);
        As[ks + 2][r] = tfstore(av0.z); As[ks + 3][r] = tfstore(av0.w);
        As[ks + 4][r] = tfstore(av1.x); As[ks + 5][r] = tfstore(av1.y);
        As[ks + 6][r] = tfstore(av1.z); As[ks + 7][r] = tfstore(av1.w);
        Bs[ks + 0][r] = tfstore(bv0.x); Bs[ks + 1][r] = tfstore(bv0.y);
        Bs[ks + 2][r] = tfstore(bv0.z); Bs[ks + 3][r] = tfstore(bv0.w);
        Bs[ks + 4][r] = tfstore(bv1.x); Bs[ks + 5][r] = tfstore(bv1.y);
        Bs[ks + 6][r] = tfstore(bv1.z); Bs[ks + 7][r] = tfstore(bv1.w);
        __syncthreads();
#pragma unroll
        for (int kk = 0; kk < 16; kk += 8) {
            uint32_t af[2][4];
#pragma unroll
            for (int mt = 0; mt < 2; mt++) {
                int row = wm * 32 + mt * 16;
                af[mt][0] = __float_as_uint(As[kk + tig][row + g]);
                af[mt][1] = __float_as_uint(As[kk + tig][row + g + 8]);
                af[mt][2] = __float_as_uint(As[kk + tig + 4][row + g]);
                af[mt][3] = __float_as_uint(As[kk + tig + 4][row + g + 8]);
            }
#pragma unroll
            for (int nt = 0; nt < 8; nt++) {
                int col = wn * 64 + nt * 8 + g;
                uint32_t b0 = __float_as_uint(Bs[kk + tig][col]);
                uint32_t b1 = __float_as_uint(Bs[kk + tig + 4][col]);
                mma8(acc[0][nt], af[0], b0, b1);
                mma8(acc[1][nt], af[1], b0, b1);
            }
        }
    }
#pragma unroll
    for (int mt = 0; mt < 2; mt++)
#pragma unroll
        for (int nt = 0; nt < 8; nt++) {
            int row = bm + wm * 32 + mt * 16 + g;
            int col = bn + wn * 64 + nt * 8 + tig * 2;
            C[(long)row * N + col]       = acc[mt][nt][0];
            C[(long)row * N + col + 1]   = acc[mt][nt][1];
            C[(long)(row + 8) * N + col]     = acc[mt][nt][2];
            C[(long)(row + 8) * N + col + 1] = acc[mt][nt][3];
        }
}

// ---------------- causal conv1d (KSZ=4) + SiLU -----------------------------
__global__ __launch_bounds__(256) void conv_silu_kernel(
    const float* __restrict__ xinner, const float* __restrict__ cw,
    const float* __restrict__ cb, float* __restrict__ xconv)
{
    int idx = blockIdx.x * 256 + threadIdx.x;
    int c = idx & (INNER_ - 1);
    int token = idx >> 10;
    int s = token & (S_ - 1);
    int b = token >> 11;
    float acc = cb[c];
#pragma unroll
    for (int j = 0; j < KSZ_; j++) {
        int sp = s - (KSZ_ - 1) + j;
        if (sp >= 0) acc += xinner[(long)(b * S_ + sp) * I2_ + c] * cw[c * KSZ_ + j];
    }
    xconv[idx] = acc / (1.f + __expf(-acc));
}

// ---------------- per-head q/k/v projections (64x64 per head) --------------
__global__ __launch_bounds__(256) void qkv_kernel(
    const float* __restrict__ xconv, const float* __restrict__ xinner,
    const float* __restrict__ Wq, const float* __restrict__ Wk,
    const float* __restrict__ Wv,
    float* __restrict__ q, float* __restrict__ k, float* __restrict__ v)
{
    int tt = blockIdx.x;
    int h  = blockIdx.y;
    int which = blockIdx.z;
    const float* src; int srcStride; const float* W; float* dst;
    if (which == 0)      { src = xconv;  srcStride = INNER_; W = Wq; dst = q; }
    else if (which == 1) { src = xconv;  srcStride = INNER_; W = Wk; dst = k; }
    else                 { src = xinner; srcStride = I2_;    W = Wv; dst = v; }

    __shared__ float Xs[64][68];
    __shared__ float Ws[64][68];
    int tid = threadIdx.x, tx = tid & 15, ty = tid >> 4;
    int tok0 = tt * 64;
#pragma unroll
    for (int i = 0; i < 4; i++) {
        int c = tid + i * 256;
        int s = c >> 4, d0 = (c & 15) * 4;
        float4 xv = *(const float4*)&src[(long)(tok0 + s) * srcStride + h * DH_ + d0];
        float4 wv = *(const float4*)&W[h * DH_ * DH_ + s * DH_ + d0];
        Xs[d0 + 0][s] = xv.x; Xs[d0 + 1][s] = xv.y;
        Xs[d0 + 2][s] = xv.z; Xs[d0 + 3][s] = xv.w;
        Ws[d0 + 0][s] = wv.x; Ws[d0 + 1][s] = wv.y;
        Ws[d0 + 2][s] = wv.z; Ws[d0 + 3][s] = wv.w;
    }
    __syncthreads();
    float acc[4][4];
#pragma unroll
    for (int i = 0; i < 4; i++)
#pragma unroll
        for (int j = 0; j < 4; j++) acc[i][j] = 0.f;
#pragma unroll 16
    for (int d = 0; d < 64; d++) {
        float4 a = *(const float4*)&Xs[d][ty * 4];
        float4 b = *(const float4*)&Ws[d][tx * 4];
        float av[4] = {a.x,a.y,a.z,a.w};
        float bv[4] = {b.x,b.y,b.z,b.w};
#pragma unroll
        for (int i = 0; i < 4; i++)
#pragma unroll
            for (int j = 0; j < 4; j++) acc[i][j] += av[i] * bv[j];
    }
#pragma unroll
    for (int i = 0; i < 4; i++) {
        float4 o = {acc[i][0],acc[i][1],acc[i][2],acc[i][3]};
        *(float4*)&dst[(long)(tok0 + ty * 4 + i) * INNER_ + h * DH_ + tx * 4] = o;
    }
}

// ---------------- i/f gate GEMM, split-K partials ---------------------------
__global__ __launch_bounds__(256) void ifgate_partial_kernel(
    const float* __restrict__ q, const float* __restrict__ k,
    const float* __restrict__ v, const float* __restrict__ Wif,
    float* __restrict__ part)
{
    int tt = blockIdx.x;
    int z  = blockIdx.y;
    __shared__ float As[32][68];
    __shared__ float Ws[32][36];
    int tid = threadIdx.x;
    int ty = tid >> 3;
    int tx = tid & 7;
    float acc[2][4] = {{0,0,0,0},{0,0,0,0}};
    int c0 = z * 6;
    for (int cc = 0; cc < 6; cc++) {
        int e0 = (c0 + cc) * 32;
        const float* src = (e0 < 1024) ? q : (e0 < 2048) ? k : v;
        int ec = e0 & 1023;
#pragma unroll
        for (int i = 0; i < 8; i++) {
            int el = tid + i * 256; int s = el >> 5, e = el & 31;
            As[e][s] = src[(long)(tt * 64 + s) * INNER_ + ec + e];
        }
#pragma unroll
        for (int i = 0; i < 4; i++) {
            int el = tid + i * 256; int g = el >> 5, e = el & 31;
            Ws[e][g] = Wif[g * 3072 + e0 + e];
        }
        __syncthreads();
#pragma unroll 8
        for (int e = 0; e < 32; e++) {
            float a0 = As[e][ty * 2], a1 = As[e][ty * 2 + 1];
            float4 b = *(const float4*)&Ws[e][tx * 4];
            float bv[4] = {b.x,b.y,b.z,b.w};
#pragma unroll
            for (int j = 0; j < 4; j++) { acc[0][j] += a0 * bv[j]; acc[1][j] += a1 * bv[j]; }
        }
        __syncthreads();
    }
#pragma unroll
    for (int i = 0; i < 2; i++) {
        int token = tt * 64 + ty * 2 + i;
        float4 o = {acc[i][0],acc[i][1],acc[i][2],acc[i][3]};
        *(float4*)&part[((long)z * T_ + token) * 32 + tx * 4] = o;
    }
}

__global__ __launch_bounds__(256) void ifreduce_kernel(
    const float* __restrict__ part, const float* __restrict__ bif,
    float* __restrict__ ifp)
{
    int idx = blockIdx.x * 256 + threadIdx.x;
    int g = idx & 31;
    float s = 0.f;
#pragma unroll
    for (int z = 0; z < IFSPLIT; z++) s += part[(long)z * T_ * 32 + idx];
    float val = s + bif[g];
    ifp[idx] = CAP_ * tanhf(val * (1.0f / CAP_));
}

// ---------------- gate prefix scan per (b,h) --------------------------------
__global__ __launch_bounds__(256) void gate_scan_kernel(
    const float* __restrict__ ifp, float* __restrict__ gg,
    float* __restrict__ gM, float* __restrict__ gEn)
{
    const float NEGINF = -3.0e38f;
    int bh = blockIdx.x;
    int b = bh / NH_, h = bh % NH_;
    int tid = threadIdx.x;
    __shared__ float sbuf[256];
    const int VPT = 8;
    float li[VPT], cs[VPT];
    float csum = 0.f;
#pragma unroll
    for (int j = 0; j < VPT; j++) {
        int s = tid * VPT + j;
        long base = (long)(b * S_ + s) * 32;
        float f = ifp[base + 16 + h];
        li[j] = ifp[base + h];
        float ls = fminf(f, 0.f) - log1pf(__expf(-fabsf(f)));
        csum += ls;
        cs[j] = csum;
    }
    sbuf[tid] = csum; __syncthreads();
    for (int off = 1; off < 256; off <<= 1) {
        float vv = (tid >= off) ? sbuf[tid - off] : 0.f;
        __syncthreads();
        sbuf[tid] += vv;
        __syncthreads();
    }
    float excl = sbuf[tid] - csum;
    float Fc[VPT], gv[VPT], mcs[VPT];
    float mx = NEGINF;
#pragma unroll
    for (int j = 0; j < VPT; j++) {
        Fc[j] = excl + cs[j];
        gv[j] = li[j] - Fc[j];
        mx = fmaxf(mx, gv[j]);
        mcs[j] = mx;
    }
    __syncthreads();
    sbuf[tid] = mx; __syncthreads();
    for (int off = 1; off < 256; off <<= 1) {
        float vv = (tid >= off) ? sbuf[tid - off] : NEGINF;
        __syncthreads();
        sbuf[tid] = fmaxf(sbuf[tid], vv);
        __syncthreads();
    }
    float emax = (tid == 0) ? NEGINF : sbuf[tid - 1];
#pragma unroll
    for (int j = 0; j < VPT; j++) {
        int s = tid * VPT + j;
        long o = (long)bh * S_ + s;
        float M = fmaxf(emax, mcs[j]);
        gg[o] = gv[j];
        gM[o] = M;
        gEn[o] = __expf(-(Fc[j] + M));
    }
}

// ---------------- mLSTM attention (tf32 mma, t-major conflict-free) ---------
#define VSTR 88
__global__ __launch_bounds__(256) void mlstm_attn_tf32(
    const float* __restrict__ q, const float* __restrict__ k,
    const float* __restrict__ v, const float* __restrict__ gg,
    const float* __restrict__ gM, const float* __restrict__ gEn,
    const float* __restrict__ xinner, const float* __restrict__ xconv,
    const float* __restrict__ norm_w, const float* __restrict__ skip,
    float* __restrict__ hout)
{
    int bh = blockIdx.y;
    int b = bh >> 4, h = bh & 15;
    extern __shared__ float sm[];
    float* Qs  = sm;                 // [64][68] s-major: Qs[s*68+d]
    float* Ks  = Qs + 64 * 68;       // [64][68] t-major: Ks[t*68+d]; later H[s][d]
    float* Ps  = Ks + 64 * 68;       // [64][68] s-major
    float* Vs  = Ps + 64 * 68;       // [64][VSTR] t-major (col 64 = ones)
    float* Msv = Vs + 64 * VSTR;     // [64]
    float* gsv = Msv + 64;           // [64]
    float* rsv = gsv + 64;           // [64]

    int tid = threadIdx.x;
    int warp = tid >> 5, lane = tid & 31;
    int wm = warp & 3, wn = warp >> 2;
    int g = lane >> 2, tig = lane & 3;
    int srow0 = wm * 16 + g, srow1 = srow0 + 8;

    // init Vs columns 64..VSTR-1: ones at 64, zeros elsewhere (once per block)
    for (int i = tid; i < 64 * (VSTR - 64); i += 256) {
        int t = i / (VSTR - 64), c = i % (VSTR - 64);
        Vs[t * VSTR + 64 + c] = (c == 0) ? 1.0f : 0.0f;
    }

    for (int rep = 0; rep < 2; rep++) {
        int qt = rep ? (31 - (int)blockIdx.x) : (int)blockIdx.x;
        int tok0 = b * S_ + qt * 64;

        __syncthreads();
#pragma unroll
        for (int i = 0; i < 4; i++) {
            int c = tid + i * 256; int s = c >> 4, d0 = (c & 15) * 4;
            float4 qv = *(const float4*)&q[(long)(tok0 + s) * INNER_ + h * DH_ + d0];
            float4 o = {tfstore(qv.x), tfstore(qv.y), tfstore(qv.z), tfstore(qv.w)};
            *(float4*)&Qs[s * 68 + d0] = o;
        }
        if (tid < 64) Msv[tid] = gM[(long)bh * S_ + qt * 64 + tid];
        __syncthreads();
        float Mi0 = Msv[srow0], Mi1 = Msv[srow1];

        // hoist Q fragments (constant over kt loop)
        uint32_t qf[8][4];
#pragma unroll
        for (int k08 = 0; k08 < 8; k08++) {
            int k0 = k08 * 8;
            qf[k08][0] = __float_as_uint(Qs[srow0 * 68 + k0 + tig]);
            qf[k08][1] = __float_as_uint(Qs[srow1 * 68 + k0 + tig]);
            qf[k08][2] = __float_as_uint(Qs[srow0 * 68 + k0 + tig + 4]);
            qf[k08][3] = __float_as_uint(Qs[srow1 * 68 + k0 + tig + 4]);
        }

        float acc[5][4];
#pragma unroll
        for (int nt = 0; nt < 5; nt++)
#pragma unroll
            for (int i = 0; i < 4; i++) acc[nt][i] = 0.f;

        for (int kt = 0; kt <= qt; kt++) {
            __syncthreads();   // prev readers done with Ks/Vs/gsv
            int ktok = b * S_ + kt * 64;
            // t-major conflict-free float4 fill (LDG.128 -> STS.128)
#pragma unroll
            for (int i = 0; i < 4; i++) {
                int c = tid + i * 256; int t = c >> 4, d0 = (c & 15) * 4;
                float4 kv = *(const float4*)&k[(long)(ktok + t) * INNER_ + h * DH_ + d0];
                float4 vv = *(const float4*)&v[(long)(ktok + t) * INNER_ + h * DH_ + d0];
                float4 ko = {tfstore(kv.x), tfstore(kv.y), tfstore(kv.z), tfstore(kv.w)};
                float4 vo = {tfstore(vv.x), tfstore(vv.y), tfstore(vv.z), tfstore(vv.w)};
                *(float4*)&Ks[t * 68 + d0] = ko;
                *(float4*)&Vs[t * VSTR + d0] = vo;
            }
            if (tid < 64) gsv[tid] = gg[(long)bh * S_ + kt * 64 + tid];
            __syncthreads();

            // QK^T: B[k=d][n=t] = Ks[t][d]
            float p[4][4];
#pragma unroll
            for (int nt = 0; nt < 4; nt++)
#pragma unroll
                for (int i = 0; i < 4; i++) p[nt][i] = 0.f;
#pragma unroll
            for (int k08 = 0; k08 < 8; k08++) {
                int k0 = k08 * 8;
#pragma unroll
                for (int nt = 0; nt < 4; nt++) {
                    int t = wn * 32 + nt * 8 + g;
                    uint32_t b0 = __float_as_uint(Ks[t * 68 + k0 + tig]);
                    uint32_t b1 = __float_as_uint(Ks[t * 68 + k0 + tig + 4]);
                    mma8(p[nt], qf[k08], b0, b1);
                }
            }

            // gate + mask + store P (tf32)
            bool diag = (kt == qt);
#pragma unroll
            for (int nt = 0; nt < 4; nt++) {
                int c0c = wn * 32 + nt * 8 + tig * 2;
                float gv0 = gsv[c0c], gv1 = gsv[c0c + 1];
                float e00 = (diag && c0c     > srow0) ? 0.f : p[nt][0] * 0.125f * __expf(gv0 - Mi0);
                float e01 = (diag && c0c + 1 > srow0) ? 0.f : p[nt][1] * 0.125f * __expf(gv1 - Mi0);
                float e10 = (diag && c0c     > srow1) ? 0.f : p[nt][2] * 0.125f * __expf(gv0 - Mi1);
                float e11 = (diag && c0c + 1 > srow1) ? 0.f : p[nt][3] * 0.125f * __expf(gv1 - Mi1);
                Ps[srow0 * 68 + c0c]     = tfstore(e00);
                Ps[srow0 * 68 + c0c + 1] = tfstore(e01);
                Ps[srow1 * 68 + c0c]     = tfstore(e10);
                Ps[srow1 * 68 + c0c + 1] = tfstore(e11);
            }
            __syncthreads();

            // P @ [V | 1]: B[k=t][n=d] = Vs[t][d]
#pragma unroll
            for (int k08 = 0; k08 < 8; k08++) {
                int k0 = k08 * 8;
                uint32_t af[4];
                af[0] = __float_as_uint(Ps[srow0 * 68 + k0 + tig]);
                af[1] = __float_as_uint(Ps[srow1 * 68 + k0 + tig]);
                af[2] = __float_as_uint(Ps[srow0 * 68 + k0 + tig + 4]);
                af[3] = __float_as_uint(Ps[srow1 * 68 + k0 + tig + 4]);
#pragma unroll
                for (int nt = 0; nt < 5; nt++) {
                    int d = wn * 40 + nt * 8 + g;
                    uint32_t b0 = __float_as_uint(Vs[(k0 + tig) * VSTR + d]);
                    uint32_t b1 = __float_as_uint(Vs[(k0 + tig + 4) * VSTR + d]);
                    mma8(acc[nt], af, b0, b1);
                }
            }
        }
        __syncthreads();

        // write H into Ks scratch ([s][d] stride 68) and rsum into rsv
#pragma unroll
        for (int nt = 0; nt < 5; nt++) {
            int dcol = wn * 40 + nt * 8 + tig * 2;
            if (dcol < 64) {
                Ks[srow0 * 68 + dcol]     = acc[nt][0];
                Ks[srow0 * 68 + dcol + 1] = acc[nt][1];
                Ks[srow1 * 68 + dcol]     = acc[nt][2];
                Ks[srow1 * 68 + dcol + 1] = acc[nt][3];
            } else if (dcol == 64) {
                rsv[srow0] = acc[nt][0];
                rsv[srow1] = acc[nt][2];
            }
        }
        __syncthreads();

        // epilogue
        int r2 = tid >> 2, qd = tid & 3;
        float n = fmaxf(fabsf(rsv[r2]), gEn[(long)bh * S_ + qt * 64 + r2]);
        float inv = 1.f / (n + EPS_);
        float hv[16];
        float ss = 0.f;
#pragma unroll
        for (int u = 0; u < 16; u++) {
            hv[u] = Ks[r2 * 68 + qd * 16 + u] * inv;
            ss += hv[u] * hv[u];
        }
        Qs[r2 * 4 + qd] = ss;
        __syncthreads();
        float sumsq = Qs[r2 * 4 + 0] + Qs[r2 * 4 + 1] + Qs[r2 * 4 + 2] + Qs[r2 * 4 + 3];
        float rrms = rsqrtf(sumsq * (1.f / 64.f) + NORM_EPS_);
        int token = tok0 + r2;
#pragma unroll
        for (int u = 0; u < 16; u++) {
            int c = h * DH_ + qd * 16 + u;
            float hn = hv[u] * rrms * (1.f + norm_w[c]);
            float ht = hn + skip[c] * xconv[(long)token * INNER_ + c];
            float z = xinner[(long)token * I2_ + INNER_ + c];
            float out = ht * (z / (1.f + __expf(-z)));
            hout[(long)token * INNER_ + c] = out;
        }
    }
}

// ---------------------------------------------------------------------------
extern "C" void kernel_launch(void* const* d_in, const int* in_sizes, int n_in,
                              void* d_out, int out_size)
{
    const float* x      = (const float*)d_in[0];
    const float* W_up   = (const float*)d_in[1];
    const float* W_q    = (const float*)d_in[2];
    const float* W_k    = (const float*)d_in[3];
    const float* W_v    = (const float*)d_in[4];
    const float* conv_w = (const float*)d_in[5];
    const float* conv_b = (const float*)d_in[6];
    const float* W_if   = (const float*)d_in[7];
    const float* b_if   = (const float*)d_in[8];
    const float* norm_w = (const float*)d_in[9];
    const float* skip   = (const float*)d_in[10];
    const float* W_down = (const float*)d_in[11];
    float* out = (float*)d_out;

    float *xinner, *xconv, *qp, *kp, *vp, *ifpart, *ifp, *gv, *Mv, *env, *hout;
    cudaGetSymbolAddress((void**)&xinner, g_xinner);
    cudaGetSymbolAddress((void**)&xconv,  g_xconv);
    cudaGetSymbolAddress((void**)&qp,     g_q);
    cudaGetSymbolAddress((void**)&kp,     g_k);
    cudaGetSymbolAddress((void**)&vp,     g_v);
    cudaGetSymbolAddress((void**)&ifpart, g_ifpart);
    cudaGetSymbolAddress((void**)&ifp,    g_if);
    cudaGetSymbolAddress((void**)&gv,     g_gv);
    cudaGetSymbolAddress((void**)&Mv,     g_Mv);
    cudaGetSymbolAddress((void**)&env,    g_env);
    cudaGetSymbolAddress((void**)&hout,   g_hout);

    // Qs+Ks+Ps (3*64*68) + Vs (64*88) + Msv/gsv/rsv (192)
    const int ATTN_SMEM = (3 * 64 * 68 + 64 * VSTR + 192) * (int)sizeof(float);
    cudaFuncSetAttribute(mlstm_attn_tf32,
                         cudaFuncAttributeMaxDynamicSharedMemorySize, ATTN_SMEM);

    gemm_nt_tf32<<<dim3(I2_ / 128, T_ / 128), 256>>>(x, W_up, xinner, T_, I2_, DIM_);
    conv_silu_kernel<<<(T_ * INNER_) / 256, 256>>>(xinner, conv_w, conv_b, xconv);
    qkv_kernel<<<dim3(T_ / 64, NH_, 3), 256>>>(xconv, xinner, W_q, W_k, W_v, qp, kp, vp);
    ifgate_partial_kernel<<<dim3(T_ / 64, IFSPLIT), 256>>>(qp, kp, vp, W_if, ifpart);
    ifreduce_kernel<<<(T_ * 32) / 256, 256>>>(ifpart, b_if, ifp);
    gate_scan_kernel<<<B_ * NH_, 256>>>(ifp, gv, Mv, env);
    mlstm_attn_tf32<<<dim3(S_ / 128, B_ * NH_), 256, ATTN_SMEM>>>(
        qp, kp, vp, gv, Mv, env, xinner, xconv, norm_w, skip, hout);
    gemm_nt_tf32<<<dim3(DIM_ / 128, T_ / 128), 256>>>(hout, W_down, out, T_, DIM_, INNER_);
}

// round 6
// speedup vs baseline: 1.2063x; 1.0003x over previous
#include <cuda_runtime.h>
#include <cuda_bf16.h>
#include <cstdint>

#define B_   2
#define S_   2048
#define T_   4096          // B*S
#define DIM_ 512
#define INNER_ 1024
#define I2_  2048
#define NH_  16
#define DH_  64
#define KSZ_ 4
#define EPS_ 5e-5f
#define NORM_EPS_ 1e-6f
#define CAP_ 15.0f
#define IFSPLIT 16

// ---------------- scratch (device globals; no allocation allowed) ----------
__device__ float g_xinner[T_ * I2_];
__device__ float g_xconv [T_ * INNER_];
__device__ float g_q     [T_ * INNER_];
__device__ float g_k     [T_ * INNER_];
__device__ float g_v     [T_ * INNER_];
__device__ float g_ifpart[IFSPLIT * T_ * 32];
__device__ float g_if    [T_ * 32];
__device__ float g_gv    [B_ * NH_ * S_];
__device__ float g_Mv    [B_ * NH_ * S_];
__device__ float g_env   [B_ * NH_ * S_];
__device__ float g_hout  [T_ * INNER_];

// ---------------- tf32 mma helpers -----------------------------------------
__device__ __forceinline__ float tfstore(float x) {
    uint32_t r; asm("cvt.rna.tf32.f32 %0, %1;" : "=r"(r) : "f"(x));
    return __uint_as_float(r);
}
__device__ __forceinline__ void mma8(float* c, const uint32_t* a,
                                     uint32_t b0, uint32_t b1) {
    asm volatile(
        "mma.sync.aligned.m16n8k8.row.col.f32.tf32.tf32.f32 "
        "{%0,%1,%2,%3}, {%4,%5,%6,%7}, {%8,%9}, {%0,%1,%2,%3};"
        : "+f"(c[0]), "+f"(c[1]), "+f"(c[2]), "+f"(c[3])
        : "r"(a[0]), "r"(a[1]), "r"(a[2]), "r"(a[3]), "r"(b0), "r"(b1));
}

// ---------------- tf32 NT GEMM: C[M,N] = A[M,K] * B[N,K]^T ------------------
__global__ __launch_bounds__(256) void gemm_nt_tf32(
    const float* __restrict__ A, const float* __restrict__ Bm,
    float* __restrict__ C, int M, int N, int K)
{
    __shared__ float As[16][136];
    __shared__ float Bs[16][136];
    int bm = blockIdx.y * 128, bn = blockIdx.x * 128;
    int tid = threadIdx.x;
    int warp = tid >> 5, lane = tid & 31;
    int wm = warp & 3;
    int wn = warp >> 2;
    int g = lane >> 2, tig = lane & 3;
    float acc[2][8][4];
#pragma unroll
    for (int mt = 0; mt < 2; mt++)
#pragma unroll
        for (int nt = 0; nt < 8; nt++)
#pragma unroll
            for (int i = 0; i < 4; i++) acc[mt][nt][i] = 0.f;

    int r = tid >> 1, ks = (tid & 1) * 8;
    const float* Ag = A + (long)(bm + r) * K + ks;
    const float* Bg = Bm + (long)(bn + r) * K + ks;

    for (int k0 = 0; k0 < K; k0 += 16) {
        float4 av0 = *(const float4*)(Ag + k0);
        float4 av1 = *(const float4*)(Ag + k0 + 4);
        float4 bv0 = *(const float4*)(Bg + k0);
        float4 bv1 = *(const float4*)(Bg + k0 + 4);
        __syncthreads();
        As[ks + 0][r] = tfstore(av0.x); As[ks + 1][r] = tfstore(av0.y);
        As[ks + 2][r] = tfstore(av0.z); As[ks + 3][r] = tfstore(av0.w);
        As[ks + 4][r] = tfstore(av1.x); As[ks + 5][r] = tfstore(av1.y);
        As[ks + 6][r] = tfstore(av1.z); As[ks + 7][r] = tfstore(av1.w);
        Bs[ks + 0][r] = tfstore(bv0.x); Bs[ks + 1][r] = tfstore(bv0.y);
        Bs[ks + 2][r] = tfstore(bv0.z); Bs[ks + 3][r] = tfstore(bv0.w);
        Bs[ks + 4][r] = tfstore(bv1.x); Bs[ks + 5][r] = tfstore(bv1.y);
        Bs[ks + 6][r] = tfstore(bv1.z); Bs[ks + 7][r] = tfstore(bv1.w);
        __syncthreads();
#pragma unroll
        for (int kk = 0; kk < 16; kk += 8) {
            uint32_t af[2][4];
#pragma unroll
            for (int mt = 0; mt < 2; mt++) {
                int row = wm * 32 + mt * 16;
                af[mt][0] = __float_as_uint(As[kk + tig][row + g]);
                af[mt][1] = __float_as_uint(As[kk + tig][row + g + 8]);
                af[mt][2] = __float_as_uint(As[kk + tig + 4][row + g]);
                af[mt][3] = __float_as_uint(As[kk + tig + 4][row + g + 8]);
            }
#pragma unroll
            for (int nt = 0; nt < 8; nt++) {
                int col = wn * 64 + nt * 8 + g;
                uint32_t b0 = __float_as_uint(Bs[kk + tig][col]);
                uint32_t b1 = __float_as_uint(Bs[kk + tig + 4][col]);
                mma8(acc[0][nt], af[0], b0, b1);
                mma8(acc[1][nt], af[1], b0, b1);
            }
        }
    }
#pragma unroll
    for (int mt = 0; mt < 2; mt++)
#pragma unroll
        for (int nt = 0; nt < 8; nt++) {
            int row = bm + wm * 32 + mt * 16 + g;
            int col = bn + wn * 64 + nt * 8 + tig * 2;
            C[(long)row * N + col]       = acc[mt][nt][0];
            C[(long)row * N + col + 1]   = acc[mt][nt][1];
            C[(long)(row + 8) * N + col]     = acc[mt][nt][2];
            C[(long)(row + 8) * N + col + 1] = acc[mt][nt][3];
        }
}

// ---------------- causal conv1d (KSZ=4) + SiLU -----------------------------
__global__ __launch_bounds__(256) void conv_silu_kernel(
    const float* __restrict__ xinner, const float* __restrict__ cw,
    const float* __restrict__ cb, float* __restrict__ xconv)
{
    int idx = blockIdx.x * 256 + threadIdx.x;
    int c = idx & (INNER_ - 1);
    int token = idx >> 10;
    int s = token & (S_ - 1);
    int b = token >> 11;
    float acc = cb[c];
#pragma unroll
    for (int j = 0; j < KSZ_; j++) {
        int sp = s - (KSZ_ - 1) + j;
        if (sp >= 0) acc += xinner[(long)(b * S_ + sp) * I2_ + c] * cw[c * KSZ_ + j];
    }
    xconv[idx] = acc / (1.f + __expf(-acc));
}

// ---------------- per-head q/k/v projections (64x64 per head) --------------
__global__ __launch_bounds__(256) void qkv_kernel(
    const float* __restrict__ xconv, const float* __restrict__ xinner,
    const float* __restrict__ Wq, const float* __restrict__ Wk,
    const float* __restrict__ Wv,
    float* __restrict__ q, float* __restrict__ k, float* __restrict__ v)
{
    int tt = blockIdx.x;
    int h  = blockIdx.y;
    int which = blockIdx.z;
    const float* src; int srcStride; const float* W; float* dst;
    if (which == 0)      { src = xconv;  srcStride = INNER_; W = Wq; dst = q; }
    else if (which == 1) { src = xconv;  srcStride = INNER_; W = Wk; dst = k; }
    else                 { src = xinner; srcStride = I2_;    W = Wv; dst = v; }

    __shared__ float Xs[64][68];
    __shared__ float Ws[64][68];
    int tid = threadIdx.x, tx = tid & 15, ty = tid >> 4;
    int tok0 = tt * 64;
#pragma unroll
    for (int i = 0; i < 4; i++) {
        int c = tid + i * 256;
        int s = c >> 4, d0 = (c & 15) * 4;
        float4 xv = *(const float4*)&src[(long)(tok0 + s) * srcStride + h * DH_ + d0];
        float4 wv = *(const float4*)&W[h * DH_ * DH_ + s * DH_ + d0];
        Xs[d0 + 0][s] = xv.x; Xs[d0 + 1][s] = xv.y;
        Xs[d0 + 2][s] = xv.z; Xs[d0 + 3][s] = xv.w;
        Ws[d0 + 0][s] = wv.x; Ws[d0 + 1][s] = wv.y;
        Ws[d0 + 2][s] = wv.z; Ws[d0 + 3][s] = wv.w;
    }
    __syncthreads();
    float acc[4][4];
#pragma unroll
    for (int i = 0; i < 4; i++)
#pragma unroll
        for (int j = 0; j < 4; j++) acc[i][j] = 0.f;
#pragma unroll 16
    for (int d = 0; d < 64; d++) {
        float4 a = *(const float4*)&Xs[d][ty * 4];
        float4 b = *(const float4*)&Ws[d][tx * 4];
        float av[4] = {a.x,a.y,a.z,a.w};
        float bv[4] = {b.x,b.y,b.z,b.w};
#pragma unroll
        for (int i = 0; i < 4; i++)
#pragma unroll
            for (int j = 0; j < 4; j++) acc[i][j] += av[i] * bv[j];
    }
#pragma unroll
    for (int i = 0; i < 4; i++) {
        float4 o = {acc[i][0],acc[i][1],acc[i][2],acc[i][3]};
        *(float4*)&dst[(long)(tok0 + ty * 4 + i) * INNER_ + h * DH_ + tx * 4] = o;
    }
}

// ---------------- i/f gate GEMM, split-K partials ---------------------------
__global__ __launch_bounds__(256) void ifgate_partial_kernel(
    const float* __restrict__ q, const float* __restrict__ k,
    const float* __restrict__ v, const float* __restrict__ Wif,
    float* __restrict__ part)
{
    int tt = blockIdx.x;
    int z  = blockIdx.y;
    __shared__ float As[32][68];
    __shared__ float Ws[32][36];
    int tid = threadIdx.x;
    int ty = tid >> 3;
    int tx = tid & 7;
    float acc[2][4] = {{0,0,0,0},{0,0,0,0}};
    int c0 = z * 6;
    for (int cc = 0; cc < 6; cc++) {
        int e0 = (c0 + cc) * 32;
        const float* src = (e0 < 1024) ? q : (e0 < 2048) ? k : v;
        int ec = e0 & 1023;
#pragma unroll
        for (int i = 0; i < 8; i++) {
            int el = tid + i * 256; int s = el >> 5, e = el & 31;
            As[e][s] = src[(long)(tt * 64 + s) * INNER_ + ec + e];
        }
#pragma unroll
        for (int i = 0; i < 4; i++) {
            int el = tid + i * 256; int g = el >> 5, e = el & 31;
            Ws[e][g] = Wif[g * 3072 + e0 + e];
        }
        __syncthreads();
#pragma unroll 8
        for (int e = 0; e < 32; e++) {
            float a0 = As[e][ty * 2], a1 = As[e][ty * 2 + 1];
            float4 b = *(const float4*)&Ws[e][tx * 4];
            float bv[4] = {b.x,b.y,b.z,b.w};
#pragma unroll
            for (int j = 0; j < 4; j++) { acc[0][j] += a0 * bv[j]; acc[1][j] += a1 * bv[j]; }
        }
        __syncthreads();
    }
#pragma unroll
    for (int i = 0; i < 2; i++) {
        int token = tt * 64 + ty * 2 + i;
        float4 o = {acc[i][0],acc[i][1],acc[i][2],acc[i][3]};
        *(float4*)&part[((long)z * T_ + token) * 32 + tx * 4] = o;
    }
}

__global__ __launch_bounds__(256) void ifreduce_kernel(
    const float* __restrict__ part, const float* __restrict__ bif,
    float* __restrict__ ifp)
{
    int idx = blockIdx.x * 256 + threadIdx.x;
    int g = idx & 31;
    float s = 0.f;
#pragma unroll
    for (int z = 0; z < IFSPLIT; z++) s += part[(long)z * T_ * 32 + idx];
    float val = s + bif[g];
    ifp[idx] = CAP_ * tanhf(val * (1.0f / CAP_));
}

// ---------------- gate prefix scan per (b,h) --------------------------------
__global__ __launch_bounds__(256) void gate_scan_kernel(
    const float* __restrict__ ifp, float* __restrict__ gg,
    float* __restrict__ gM, float* __restrict__ gEn)
{
    const float NEGINF = -3.0e38f;
    int bh = blockIdx.x;
    int b = bh / NH_, h = bh % NH_;
    int tid = threadIdx.x;
    __shared__ float sbuf[256];
    const int VPT = 8;
    float li[VPT], cs[VPT];
    float csum = 0.f;
#pragma unroll
    for (int j = 0; j < VPT; j++) {
        int s = tid * VPT + j;
        long base = (long)(b * S_ + s) * 32;
        float f = ifp[base + 16 + h];
        li[j] = ifp[base + h];
        float ls = fminf(f, 0.f) - log1pf(__expf(-fabsf(f)));
        csum += ls;
        cs[j] = csum;
    }
    sbuf[tid] = csum; __syncthreads();
    for (int off = 1; off < 256; off <<= 1) {
        float vv = (tid >= off) ? sbuf[tid - off] : 0.f;
        __syncthreads();
        sbuf[tid] += vv;
        __syncthreads();
    }
    float excl = sbuf[tid] - csum;
    float Fc[VPT], gv[VPT], mcs[VPT];
    float mx = NEGINF;
#pragma unroll
    for (int j = 0; j < VPT; j++) {
        Fc[j] = excl + cs[j];
        gv[j] = li[j] - Fc[j];
        mx = fmaxf(mx, gv[j]);
        mcs[j] = mx;
    }
    __syncthreads();
    sbuf[tid] = mx; __syncthreads();
    for (int off = 1; off < 256; off <<= 1) {
        float vv = (tid >= off) ? sbuf[tid - off] : NEGINF;
        __syncthreads();
        sbuf[tid] = fmaxf(sbuf[tid], vv);
        __syncthreads();
    }
    float emax = (tid == 0) ? NEGINF : sbuf[tid - 1];
#pragma unroll
    for (int j = 0; j < VPT; j++) {
        int s = tid * VPT + j;
        long o = (long)bh * S_ + s;
        float M = fmaxf(emax, mcs[j]);
        gg[o] = gv[j];
        gM[o] = M;
        gEn[o] = __expf(-(Fc[j] + M));
    }
}

// ---------------- mLSTM attention (tf32 mma, t-major conflict-free) ---------
#define VSTR 88
__global__ __launch_bounds__(256) void mlstm_attn_tf32(
    const float* __restrict__ q, const float* __restrict__ k,
    const float* __restrict__ v, const float* __restrict__ gg,
    const float* __restrict__ gM, const float* __restrict__ gEn,
    const float* __restrict__ xinner, const float* __restrict__ xconv,
    const float* __restrict__ norm_w, const float* __restrict__ skip,
    float* __restrict__ hout)
{
    int bh = blockIdx.y;
    int b = bh >> 4, h = bh & 15;
    extern __shared__ float sm[];
    float* Qs  = sm;                 // [64][68] s-major: Qs[s*68+d]
    float* Ks  = Qs + 64 * 68;       // [64][68] t-major: Ks[t*68+d]; later H[s][d]
    float* Ps  = Ks + 64 * 68;       // [64][68] s-major
    float* Vs  = Ps + 64 * 68;       // [64][VSTR] t-major (col 64 = ones)
    float* Msv = Vs + 64 * VSTR;     // [64]
    float* gsv = Msv + 64;           // [64]
    float* rsv = gsv + 64;           // [64]

    int tid = threadIdx.x;
    int warp = tid >> 5, lane = tid & 31;
    int wm = warp & 3, wn = warp >> 2;
    int g = lane >> 2, tig = lane & 3;
    int srow0 = wm * 16 + g, srow1 = srow0 + 8;

    // init Vs columns 64..VSTR-1: ones at 64, zeros elsewhere (once per block)
    for (int i = tid; i < 64 * (VSTR - 64); i += 256) {
        int t = i / (VSTR - 64), c = i % (VSTR - 64);
        Vs[t * VSTR + 64 + c] = (c == 0) ? 1.0f : 0.0f;
    }

    for (int rep = 0; rep < 2; rep++) {
        int qt = rep ? (31 - (int)blockIdx.x) : (int)blockIdx.x;
        int tok0 = b * S_ + qt * 64;

        __syncthreads();
#pragma unroll
        for (int i = 0; i < 4; i++) {
            int c = tid + i * 256; int s = c >> 4, d0 = (c & 15) * 4;
            float4 qv = *(const float4*)&q[(long)(tok0 + s) * INNER_ + h * DH_ + d0];
            float4 o = {tfstore(qv.x), tfstore(qv.y), tfstore(qv.z), tfstore(qv.w)};
            *(float4*)&Qs[s * 68 + d0] = o;
        }
        if (tid < 64) Msv[tid] = gM[(long)bh * S_ + qt * 64 + tid];
        __syncthreads();
        float Mi0 = Msv[srow0], Mi1 = Msv[srow1];

        // hoist Q fragments (constant over kt loop)
        uint32_t qf[8][4];
#pragma unroll
        for (int k08 = 0; k08 < 8; k08++) {
            int k0 = k08 * 8;
            qf[k08][0] = __float_as_uint(Qs[srow0 * 68 + k0 + tig]);
            qf[k08][1] = __float_as_uint(Qs[srow1 * 68 + k0 + tig]);
            qf[k08][2] = __float_as_uint(Qs[srow0 * 68 + k0 + tig + 4]);
            qf[k08][3] = __float_as_uint(Qs[srow1 * 68 + k0 + tig + 4]);
        }

        float acc[5][4];
#pragma unroll
        for (int nt = 0; nt < 5; nt++)
#pragma unroll
            for (int i = 0; i < 4; i++) acc[nt][i] = 0.f;

        for (int kt = 0; kt <= qt; kt++) {
            __syncthreads();   // prev readers done with Ks/Vs/gsv
            int ktok = b * S_ + kt * 64;
            // t-major conflict-free float4 fill (LDG.128 -> STS.128)
#pragma unroll
            for (int i = 0; i < 4; i++) {
                int c = tid + i * 256; int t = c >> 4, d0 = (c & 15) * 4;
                float4 kv = *(const float4*)&k[(long)(ktok + t) * INNER_ + h * DH_ + d0];
                float4 vv = *(const float4*)&v[(long)(ktok + t) * INNER_ + h * DH_ + d0];
                float4 ko = {tfstore(kv.x), tfstore(kv.y), tfstore(kv.z), tfstore(kv.w)};
                float4 vo = {tfstore(vv.x), tfstore(vv.y), tfstore(vv.z), tfstore(vv.w)};
                *(float4*)&Ks[t * 68 + d0] = ko;
                *(float4*)&Vs[t * VSTR + d0] = vo;
            }
            if (tid < 64) gsv[tid] = gg[(long)bh * S_ + kt * 64 + tid];
            __syncthreads();

            // QK^T: B[k=d][n=t] = Ks[t][d]
            float p[4][4];
#pragma unroll
            for (int nt = 0; nt < 4; nt++)
#pragma unroll
                for (int i = 0; i < 4; i++) p[nt][i] = 0.f;
#pragma unroll
            for (int k08 = 0; k08 < 8; k08++) {
                int k0 = k08 * 8;
#pragma unroll
                for (int nt = 0; nt < 4; nt++) {
                    int t = wn * 32 + nt * 8 + g;
                    uint32_t b0 = __float_as_uint(Ks[t * 68 + k0 + tig]);
                    uint32_t b1 = __float_as_uint(Ks[t * 68 + k0 + tig + 4]);
                    mma8(p[nt], qf[k08], b0, b1);
                }
            }

            // gate + mask + store P (tf32)
            bool diag = (kt == qt);
#pragma unroll
            for (int nt = 0; nt < 4; nt++) {
                int c0c = wn * 32 + nt * 8 + tig * 2;
                float gv0 = gsv[c0c], gv1 = gsv[c0c + 1];
                float e00 = (diag && c0c     > srow0) ? 0.f : p[nt][0] * 0.125f * __expf(gv0 - Mi0);
                float e01 = (diag && c0c + 1 > srow0) ? 0.f : p[nt][1] * 0.125f * __expf(gv1 - Mi0);
                float e10 = (diag && c0c     > srow1) ? 0.f : p[nt][2] * 0.125f * __expf(gv0 - Mi1);
                float e11 = (diag && c0c + 1 > srow1) ? 0.f : p[nt][3] * 0.125f * __expf(gv1 - Mi1);
                Ps[srow0 * 68 + c0c]     = tfstore(e00);
                Ps[srow0 * 68 + c0c + 1] = tfstore(e01);
                Ps[srow1 * 68 + c0c]     = tfstore(e10);
                Ps[srow1 * 68 + c0c + 1] = tfstore(e11);
            }
            __syncthreads();

            // P @ [V | 1]: B[k=t][n=d] = Vs[t][d]
#pragma unroll
            for (int k08 = 0; k08 < 8; k08++) {
                int k0 = k08 * 8;
                uint32_t af[4];
                af[0] = __float_as_uint(Ps[srow0 * 68 + k0 + tig]);
                af[1] = __float_as_uint(Ps[srow1 * 68 + k0 + tig]);
                af[2] = __float_as_uint(Ps[srow0 * 68 + k0 + tig + 4]);
                af[3] = __float_as_uint(Ps[srow1 * 68 + k0 + tig + 4]);
#pragma unroll
                for (int nt = 0; nt < 5; nt++) {
                    int d = wn * 40 + nt * 8 + g;
                    uint32_t b0 = __float_as_uint(Vs[(k0 + tig) * VSTR + d]);
                    uint32_t b1 = __float_as_uint(Vs[(k0 + tig + 4) * VSTR + d]);
                    mma8(acc[nt], af, b0, b1);
                }
            }
        }
        __syncthreads();

        // write H into Ks scratch ([s][d] stride 68) and rsum into rsv
#pragma unroll
        for (int nt = 0; nt < 5; nt++) {
            int dcol = wn * 40 + nt * 8 + tig * 2;
            if (dcol < 64) {
                Ks[srow0 * 68 + dcol]     = acc[nt][0];
                Ks[srow0 * 68 + dcol + 1] = acc[nt][1];
                Ks[srow1 * 68 + dcol]     = acc[nt][2];
                Ks[srow1 * 68 + dcol + 1] = acc[nt][3];
            } else if (dcol == 64) {
                rsv[srow0] = acc[nt][0];
                rsv[srow1] = acc[nt][2];
            }
        }
        __syncthreads();

        // epilogue
        int r2 = tid >> 2, qd = tid & 3;
        float n = fmaxf(fabsf(rsv[r2]), gEn[(long)bh * S_ + qt * 64 + r2]);
        float inv = 1.f / (n + EPS_);
        float hv[16];
        float ss = 0.f;
#pragma unroll
        for (int u = 0; u < 16; u++) {
            hv[u] = Ks[r2 * 68 + qd * 16 + u] * inv;
            ss += hv[u] * hv[u];
        }
        Qs[r2 * 4 + qd] = ss;
        __syncthreads();
        float sumsq = Qs[r2 * 4 + 0] + Qs[r2 * 4 + 1] + Qs[r2 * 4 + 2] + Qs[r2 * 4 + 3];
        float rrms = rsqrtf(sumsq * (1.f / 64.f) + NORM_EPS_);
        int token = tok0 + r2;
#pragma unroll
        for (int u = 0; u < 16; u++) {
            int c = h * DH_ + qd * 16 + u;
            float hn = hv[u] * rrms * (1.f + norm_w[c]);
            float ht = hn + skip[c] * xconv[(long)token * INNER_ + c];
            float z = xinner[(long)token * I2_ + INNER_ + c];
            float out = ht * (z / (1.f + __expf(-z)));
            hout[(long)token * INNER_ + c] = out;
        }
    }
}

// ---------------------------------------------------------------------------
extern "C" void kernel_launch(void* const* d_in, const int* in_sizes, int n_in,
                              void* d_out, int out_size)
{
    const float* x      = (const float*)d_in[0];
    const float* W_up   = (const float*)d_in[1];
    const float* W_q    = (const float*)d_in[2];
    const float* W_k    = (const float*)d_in[3];
    const float* W_v    = (const float*)d_in[4];
    const float* conv_w = (const float*)d_in[5];
    const float* conv_b = (const float*)d_in[6];
    const float* W_if   = (const float*)d_in[7];
    const float* b_if   = (const float*)d_in[8];
    const float* norm_w = (const float*)d_in[9];
    const float* skip   = (const float*)d_in[10];
    const float* W_down = (const float*)d_in[11];
    float* out = (float*)d_out;

    float *xinner, *xconv, *qp, *kp, *vp, *ifpart, *ifp, *gv, *Mv, *env, *hout;
    cudaGetSymbolAddress((void**)&xinner, g_xinner);
    cudaGetSymbolAddress((void**)&xconv,  g_xconv);
    cudaGetSymbolAddress((void**)&qp,     g_q);
    cudaGetSymbolAddress((void**)&kp,     g_k);
    cudaGetSymbolAddress((void**)&vp,     g_v);
    cudaGetSymbolAddress((void**)&ifpart, g_ifpart);
    cudaGetSymbolAddress((void**)&ifp,    g_if);
    cudaGetSymbolAddress((void**)&gv,     g_gv);
    cudaGetSymbolAddress((void**)&Mv,     g_Mv);
    cudaGetSymbolAddress((void**)&env,    g_env);
    cudaGetSymbolAddress((void**)&hout,   g_hout);

    // Qs+Ks+Ps (3*64*68) + Vs (64*88) + Msv/gsv/rsv (192)
    const int ATTN_SMEM = (3 * 64 * 68 + 64 * VSTR + 192) * (int)sizeof(float);
    cudaFuncSetAttribute(mlstm_attn_tf32,
                         cudaFuncAttributeMaxDynamicSharedMemorySize, ATTN_SMEM);

    gemm_nt_tf32<<<dim3(I2_ / 128, T_ / 128), 256>>>(x, W_up, xinner, T_, I2_, DIM_);
    conv_silu_kernel<<<(T_ * INNER_) / 256, 256>>>(xinner, conv_w, conv_b, xconv);
    qkv_kernel<<<dim3(T_ / 64, NH_, 3), 256>>>(xconv, xinner, W_q, W_k, W_v, qp, kp, vp);
    ifgate_partial_kernel<<<dim3(T_ / 64, IFSPLIT), 256>>>(qp, kp, vp, W_if, ifpart);
    ifreduce_kernel<<<(T_ * 32) / 256, 256>>>(ifpart, b_if, ifp);
    gate_scan_kernel<<<B_ * NH_, 256>>>(ifp, gv, Mv, env);
    mlstm_attn_tf32<<<dim3(S_ / 128, B_ * NH_), 256, ATTN_SMEM>>>(
        qp, kp, vp, gv, Mv, env, xinner, xconv, norm_w, skip, hout);
    gemm_nt_tf32<<<dim3(DIM_ / 128, T_ / 128), 256>>>(hout, W_down, out, T_, DIM_, INNER_);
}